// round 12
// baseline (speedup 1.0000x reference)
#include <cuda_runtime.h>

typedef unsigned long long u64;

#define BB 8
#define CC 64
#define DD 32
#define HH 64
#define WW 64
#define SS (DD*HH*WW)      /* 131072 spatial per batch */
#define PLANE (HH*WW)      /* 4096 */
#define S4 (SS/4)          /* 32768 */

// Scratch: channel-reduced (avg,max) INTERLEAVED as float2, layout [B][D][H][W].
__device__ __align__(16) float2 g_am[BB*SS];

// ---------------------------------------------------------------------------
// Pass 1: channel mean + max. One thread = 4 consecutive w elements (float4).
// Measured at ~6.6 TB/s — HBM path cap. Unchanged.
// ---------------------------------------------------------------------------
__global__ __launch_bounds__(256) void reduce_kernel(const float* __restrict__ x) {
    int tid = blockIdx.x * blockDim.x + threadIdx.x;   // 0 .. 262143
    int b    = tid >> 15;
    int off4 = tid & (S4 - 1);

    const float4* base = reinterpret_cast<const float4*>(x)
                       + (size_t)b * CC * S4 + off4;

    float4 s = make_float4(0.f, 0.f, 0.f, 0.f);
    float4 m = make_float4(-3.402823466e38f, -3.402823466e38f,
                           -3.402823466e38f, -3.402823466e38f);

    #pragma unroll 8
    for (int c = 0; c < CC; ++c) {
        float4 v = __ldg(base + (size_t)c * S4);
        s.x += v.x; s.y += v.y; s.z += v.z; s.w += v.w;
        m.x = fmaxf(m.x, v.x); m.y = fmaxf(m.y, v.y);
        m.z = fmaxf(m.z, v.z); m.w = fmaxf(m.w, v.w);
    }

    const float inv = 1.0f / 64.0f;
    float4* o = reinterpret_cast<float4*>(g_am + (size_t)b * SS + 4 * (size_t)off4);
    o[0] = make_float4(s.x * inv, m.x, s.y * inv, m.y);
    o[1] = make_float4(s.z * inv, m.z, s.w * inv, m.w);
}

// ---------------------------------------------------------------------------
// Packed f32x2 + smem helpers.
// ---------------------------------------------------------------------------
__device__ __forceinline__ u64 ffma2(u64 a, u64 b, u64 c) {
    u64 d;
    asm("fma.rn.f32x2 %0, %1, %2, %3;" : "=l"(d) : "l"(a), "l"(b), "l"(c));
    return d;
}
__device__ __forceinline__ u64 pack2(float lo, float hi) {
    u64 r;
    asm("mov.b64 %0, {%1, %2};" : "=l"(r) : "f"(lo), "f"(hi));
    return r;
}
__device__ __forceinline__ float2 unpack2(u64 v) {
    float2 f;
    asm("mov.b64 {%0, %1}, %2;" : "=f"(f.x), "=f"(f.y) : "l"(v));
    return f;
}
// volatile so ptxas cannot hoist weight loads back into 54 live registers
__device__ __forceinline__ u64 lds64v(unsigned addr) {
    u64 v;
    asm volatile("ld.shared.b64 %0, [%1];" : "=l"(v) : "r"(addr));
    return v;
}

// ---------------------------------------------------------------------------
// Pass 2: 3x3x3 SAME conv (avg,max -> 1 ch) + sigmoid.
// One thread = w-pair x d-chunk of 4. Sliding-plane rotation with compile-time
// accumulator trimming (exactly 27 fma2 per output = optimal) and weights in
// SMEM (uniform broadcast LDS.64 per tap) instead of 54 registers.
// ---------------------------------------------------------------------------

// accumulate plane p = d0-1+S into selected rotating accumulators:
//   A0 -> out[p-1] (kd=2, w[18+i]), A1 -> out[p] (kd=1, w[9+i]),
//   A2 -> out[p+1] (kd=0, w[i])
#define PLANE_STEP(S, A0, A1, A2, POK)                                        \
  {                                                                           \
    aX2 = 0; aY2 = 0;                                                         \
    if (POK) {                                                                \
      const u64* pp = gam + (d0 - 1 + (S)) * PLANE + h * WW + wp;             \
      u64 v[3][4];                                                            \
      _Pragma("unroll")                                                       \
      for (int kh = 0; kh < 3; ++kh) {                                        \
        bool rok = (kh == 0) ? r0ok : ((kh == 2) ? r2ok : true);              \
        const u64* rp = pp + (kh - 1) * WW;                                   \
        v[kh][0] = (rok && c0ok) ? __ldg(rp - 1) : 0ULL;                      \
        v[kh][1] =  rok          ? __ldg(rp    ) : 0ULL;                      \
        v[kh][2] =  rok          ? __ldg(rp + 1) : 0ULL;                      \
        v[kh][3] = (rok && c3ok) ? __ldg(rp + 2) : 0ULL;                      \
      }                                                                       \
      _Pragma("unroll")                                                       \
      for (int kh = 0; kh < 3; ++kh) {                                        \
        _Pragma("unroll")                                                     \
        for (int kw = 0; kw < 3; ++kw) {                                      \
          const int i = kh * 3 + kw;                                          \
          u64 vx = v[kh][kw];                                                 \
          u64 vy = v[kh][kw + 1];                                             \
          if (A0) { u64 wv = lds64v(swb + (18 + i) * 8);                      \
                    aX0 = ffma2(vx, wv, aX0); aY0 = ffma2(vy, wv, aY0); }     \
          if (A1) { u64 wv = lds64v(swb + (9 + i) * 8);                       \
                    aX1 = ffma2(vx, wv, aX1); aY1 = ffma2(vy, wv, aY1); }     \
          if (A2) { u64 wv = lds64v(swb + i * 8);                             \
                    aX2 = ffma2(vx, wv, aX2); aY2 = ffma2(vy, wv, aY2); }     \
        }                                                                     \
      }                                                                       \
    }                                                                         \
  }

#define EMIT(S)                                                               \
  {                                                                           \
    int od = d0 + (S) - 2;                                                    \
    float2 fx = unpack2(aX0), fy = unpack2(aY0);                              \
    float2 o;                                                                 \
    o.x = 1.0f / (1.0f + __expf(-(fx.x + fx.y)));                             \
    o.y = 1.0f / (1.0f + __expf(-(fy.x + fy.y)));                             \
    *reinterpret_cast<float2*>(ob + od * PLANE + h * WW + wp) = o;            \
  }

#define ROT() { aX0 = aX1; aY0 = aY1; aX1 = aX2; aY1 = aY2; }

__global__ __launch_bounds__(256, 3) void conv_kernel(const float* __restrict__ Wt,
                                                      float* __restrict__ out) {
    __shared__ u64 sw[27];
    int t = threadIdx.x;
    if (t < 27) sw[t] = pack2(__ldg(Wt + t), __ldg(Wt + 27 + t));
    __syncthreads();

    unsigned swb;
    asm("{ .reg .u64 a; cvta.to.shared.u64 a, %1; cvt.u32.u64 %0, a; }"
        : "=r"(swb) : "l"(sw));

    int g  = blockIdx.x * 256 + t;   // 0 .. 131071
    int wp = (g & 31) * 2;           // 0..62 even; outputs (wp, wp+1)
    int h  = (g >> 5) & 63;
    int dc = (g >> 11) & 7;
    int b  = g >> 14;
    int d0 = dc * 4;

    const u64* gam = reinterpret_cast<const u64*>(g_am) + (size_t)b * SS;
    float*     ob  = out + (size_t)b * SS;

    const bool r0ok = (h > 0), r2ok = (h < 63);
    const bool c0ok = (wp > 0), c3ok = (wp < 62);

    u64 aX0 = 0, aY0 = 0, aX1 = 0, aY1 = 0, aX2, aY2;

    PLANE_STEP(0, false, false, true,  (d0 > 0));          ROT();
    PLANE_STEP(1, false, true,  true,  true);              ROT();
    PLANE_STEP(2, true,  true,  true,  true);   EMIT(2);   ROT();
    PLANE_STEP(3, true,  true,  true,  true);   EMIT(3);   ROT();
    PLANE_STEP(4, true,  true,  false, true);   EMIT(4);   ROT();
    PLANE_STEP(5, true,  false, false, (d0 + 4 < DD));  EMIT(5);
}

extern "C" void kernel_launch(void* const* d_in, const int* in_sizes, int n_in,
                              void* d_out, int out_size) {
    const float* x  = (const float*)d_in[0];   // [8,64,32,64,64] fp32
    const float* Wt = (const float*)d_in[1];   // [1,2,3,3,3]     fp32
    float* out = (float*)d_out;                // [8,1,32,64,64]  fp32
    (void)in_sizes; (void)n_in; (void)out_size;

    reduce_kernel<<<1024, 256>>>(x);
    conv_kernel<<<512, 256>>>(Wt, out);
}